// round 13
// baseline (speedup 1.0000x reference)
#include <cuda_runtime.h>
#include <cuda_fp16.h>
#include <math.h>
#include <stdint.h>

#define EPS   1e-5f
#define NTHR  256

// ---- SMEM layout (bytes) ----
#define AP_OFF   0                          // Apack hi plane 32KB (embed params staged here first)
#define APL_PL   32768                      // lo plane offset
#define WB0_OFF  65536                      // 16KB chunk buf
#define WB1_OFF  81920                      // 16KB chunk buf
#define PRM_OFF  98304                      // 8 vec * 1KB
#define PS_OFF   106496                     // 1KB (4*64 floats)
#define PSQ_OFF  107520                     // 1KB
#define SMEM_TOTAL 108544                   // 106KB -> 2 CTAs/SM

// prepped fp16 weights: [gemm][chunk 8][4096 u32]; chunk = 2 kt (16KB)
// per kt: [ntp 16][lane 32] x 16B ; ntp covers nt pair (2ntp, 2ntp+1)
__device__ __align__(16) uint32_t g_wpack[4][8][4096];

__device__ __forceinline__ uint32_t s2u(const void* p) {
    uint32_t a;
    asm("{ .reg .u64 t; cvta.to.shared.u64 t, %1; cvt.u32.u64 %0, t; }" : "=r"(a) : "l"(p));
    return a;
}

__device__ __forceinline__ void hmma(float* c, const uint32_t* a, uint32_t b0, uint32_t b1) {
    asm volatile("mma.sync.aligned.m16n8k16.row.col.f32.f16.f16.f32 "
        "{%0,%1,%2,%3}, {%4,%5,%6,%7}, {%8,%9}, {%0,%1,%2,%3};"
        : "+f"(c[0]), "+f"(c[1]), "+f"(c[2]), "+f"(c[3])
        : "r"(a[0]), "r"(a[1]), "r"(a[2]), "r"(a[3]), "r"(b0), "r"(b1));
}

__device__ __forceinline__ void cp16(uint32_t dst, const void* src) {
    uint64_t gp = __cvta_generic_to_global(src);
    asm volatile("cp.async.cg.shared.global [%0], [%1], 16;" :: "r"(dst), "l"(gp));
}
#define CP_COMMIT() asm volatile("cp.async.commit_group;" ::: "memory")
#define CP_WAIT0()  asm volatile("cp.async.wait_group 0;" ::: "memory")

// 2-term fp16 split of activations
__device__ __forceinline__ void split2(float v0, float v1, uint32_t& hi, uint32_t& lo) {
    __half2 h = __floats2half2_rn(v0, v1);
    float r0 = v0 - __half2float(__low2half(h));
    float r1 = v1 - __half2float(__high2half(h));
    __half2 l = __floats2half2_rn(r0, r1);
    hi = *reinterpret_cast<uint32_t*>(&h);
    lo = *reinterpret_cast<uint32_t*>(&l);
}

__device__ __forceinline__ float gelu(float x) {
    return 0.5f * x * (1.0f + erff(x * 0.70710678118654752f));
}

// ---- prep: pack W (fp32 [k][n]) -> fragment-ready single-fp16 chunks ----
__global__ void prep_w(const float* __restrict__ W11, const float* __restrict__ W12,
                       const float* __restrict__ W21, const float* __restrict__ W22) {
    const float* Ws[4] = {W11, W12, W21, W22};
    int gi = blockIdx.x >> 3, cc = blockIdx.x & 7;
    const float* W = Ws[gi];
    for (int i = threadIdx.x; i < 4096; i += blockDim.x) {
        int kt_local = i >> 11;
        int j = i & 2047;
        int ntp = j >> 7;
        int lane = (j >> 2) & 31;
        int comp = j & 3;
        int nt = ntp * 2 + (comp >> 1);
        int which = comp & 1;
        int t = lane & 3, gg = lane >> 2;
        int n = nt * 8 + gg;
        int k = (cc * 2 + kt_local) * 16 + t * 2 + which * 8;
        __half2 r = __floats2half2_rn(W[k * 256 + n], W[(k + 1) * 256 + n]);
        g_wpack[gi][cc][i] = *reinterpret_cast<uint32_t*>(&r);
    }
}

// chunk-0 prefetch (into WB0) — overlaps preceding epilogue
__device__ __forceinline__ void prefetch_c0(uint32_t sb, const uint32_t* wsrc, int tid) {
    uint32_t d = sb + WB0_OFF + tid * 16;
    const char* s = (const char*)wsrc + tid * 16;
#pragma unroll
    for (int i = 0; i < 4; i++) cp16(d + i * 4096, s + i * 4096);
    CP_COMMIT();
}

// ---- one fused 64x256x256 GEMM (2-term fp16); chunk0 already in flight ----
// warp grid: wm in {0,1} covers M-tiles {2wm, 2wm+1}; wn in {0..3} covers nt 0..7
__device__ __forceinline__ void gemm256(const char* smem, uint32_t sb, const uint32_t* wsrc,
                                        float (&c)[2][8][4], int tid, int wn,
                                        const char* apr) {
#pragma unroll
    for (int mt = 0; mt < 2; mt++)
#pragma unroll
        for (int nt = 0; nt < 8; nt++)
#pragma unroll
            for (int q = 0; q < 4; q++) c[mt][nt][q] = 0.f;

    const uint32_t dst0 = sb + WB0_OFF + tid * 16;
    const uint32_t dst1 = sb + WB1_OFF + tid * 16;
    const char* src = (const char*)wsrc + tid * 16;
    const char* wb0 = smem + WB0_OFF + wn * 2048 + (tid & 31) * 16;
    const char* wb1 = smem + WB1_OFF + wn * 2048 + (tid & 31) * 16;

#pragma unroll
    for (int ch = 0; ch < 8; ch++) {
        CP_WAIT0();
        __syncthreads();
        if (ch + 1 < 8) {
            uint32_t d = ((ch + 1) & 1) ? dst1 : dst0;
            const char* s = src + (ch + 1) * 16384;
#pragma unroll
            for (int i = 0; i < 4; i++) cp16(d + i * 4096, s + i * 4096);
            CP_COMMIT();
        }
        const char* wb = (ch & 1) ? wb1 : wb0;
#pragma unroll
        for (int kl = 0; kl < 2; kl++) {
            const int kt = ch * 2 + kl;
            const char* ac = apr + kt * 2048;
            uint4 ah0 = *(const uint4*)(ac);
            uint4 ah1 = *(const uint4*)(ac + 128);
            uint4 al0 = *(const uint4*)(ac + APL_PL);
            uint4 al1 = *(const uint4*)(ac + APL_PL + 128);
            uint32_t ahi[2][4] = {{ah0.x, ah0.y, ah0.z, ah0.w}, {ah1.x, ah1.y, ah1.z, ah1.w}};
            uint32_t alo[2][4] = {{al0.x, al0.y, al0.z, al0.w}, {al1.x, al1.y, al1.z, al1.w}};
            const char* wbk = wb + kl * 8192;
#pragma unroll
            for (int jj = 0; jj < 4; jj++) {
                uint4 b = *(const uint4*)(wbk + jj * 512);
#pragma unroll
                for (int mt = 0; mt < 2; mt++) {
                    hmma(c[mt][jj * 2],     ahi[mt], b.x, b.y);
                    hmma(c[mt][jj * 2],     alo[mt], b.x, b.y);
                    hmma(c[mt][jj * 2 + 1], ahi[mt], b.z, b.w);
                    hmma(c[mt][jj * 2 + 1], alo[mt], b.z, b.w);
                }
            }
        }
    }
}

// rows per thread: idx(mt,h) = wm*32 + mt*16 + h*8 + g
__device__ __forceinline__ void ln_stats(float (&c)[2][8][4], float* psum, float* psq,
                                         int wn, int rowbase, int t,
                                         float (&mu)[2][2], float (&rs)[2][2]) {
    float s[2][2] = {{0, 0}, {0, 0}}, q[2][2] = {{0, 0}, {0, 0}};
#pragma unroll
    for (int mt = 0; mt < 2; mt++)
#pragma unroll
        for (int nt = 0; nt < 8; nt++) {
            s[mt][0] += c[mt][nt][0] + c[mt][nt][1];
            q[mt][0] += c[mt][nt][0] * c[mt][nt][0] + c[mt][nt][1] * c[mt][nt][1];
            s[mt][1] += c[mt][nt][2] + c[mt][nt][3];
            q[mt][1] += c[mt][nt][2] * c[mt][nt][2] + c[mt][nt][3] * c[mt][nt][3];
        }
#pragma unroll
    for (int mt = 0; mt < 2; mt++)
#pragma unroll
        for (int h = 0; h < 2; h++) {
            s[mt][h] += __shfl_xor_sync(~0u, s[mt][h], 1);
            s[mt][h] += __shfl_xor_sync(~0u, s[mt][h], 2);
            q[mt][h] += __shfl_xor_sync(~0u, q[mt][h], 1);
            q[mt][h] += __shfl_xor_sync(~0u, q[mt][h], 2);
        }
    if (t == 0) {
#pragma unroll
        for (int mt = 0; mt < 2; mt++)
#pragma unroll
            for (int h = 0; h < 2; h++) {
                int idx = rowbase + mt * 16 + h * 8;
                psum[wn * 64 + idx] = s[mt][h];
                psq[wn * 64 + idx]  = q[mt][h];
            }
    }
    __syncthreads();
#pragma unroll
    for (int mt = 0; mt < 2; mt++)
#pragma unroll
        for (int h = 0; h < 2; h++) {
            int idx = rowbase + mt * 16 + h * 8;
            float ts = psum[idx] + psum[64 + idx] + psum[128 + idx] + psum[192 + idx];
            float tq = psq[idx] + psq[64 + idx] + psq[128 + idx] + psq[192 + idx];
            float m = ts * (1.f / 256.f);
            mu[mt][h] = m;
            rs[mt][h] = rsqrtf(tq * (1.f / 256.f) - m * m + EPS);
        }
}

// writer: cell(kt=wn*4+p, t, tile=2wm+mt, g) at apw + p*2048 + mt*128, planes hi/+APL_PL
__device__ __forceinline__ void norm_split(float (&c)[2][8][4], const float* gv, const float* bv,
                                           float (&mu)[2][2], float (&rs)[2][2],
                                           char* apw, int wn, int t) {
#pragma unroll
    for (int p = 0; p < 4; p++) {
#pragma unroll
        for (int mt = 0; mt < 2; mt++) {
            uint32_t hi[4], lo[4];
#pragma unroll
            for (int e = 0; e < 2; e++) {
                int nt = 2 * p + e;
                int cg = wn * 64 + nt * 8 + t * 2;
                float2 gg = *(const float2*)(gv + cg);
                float2 bb = *(const float2*)(bv + cg);
                float v0 = (c[mt][nt][0] - mu[mt][0]) * rs[mt][0] * gg.x + bb.x;
                float v1 = (c[mt][nt][1] - mu[mt][0]) * rs[mt][0] * gg.y + bb.y;
                float v2 = (c[mt][nt][2] - mu[mt][1]) * rs[mt][1] * gg.x + bb.x;
                float v3 = (c[mt][nt][3] - mu[mt][1]) * rs[mt][1] * gg.y + bb.y;
                split2(v0, v1, hi[e * 2], lo[e * 2]);
                split2(v2, v3, hi[e * 2 + 1], lo[e * 2 + 1]);
            }
            *(uint4*)(apw + p * 2048 + mt * 128)          = make_uint4(hi[0], hi[1], hi[2], hi[3]);
            *(uint4*)(apw + p * 2048 + mt * 128 + APL_PL) = make_uint4(lo[0], lo[1], lo[2], lo[3]);
        }
    }
}

__device__ __forceinline__ void gelu_split(float (&c)[2][8][4], const float* bv,
                                           char* apw, int wn, int t) {
    __syncthreads();   // all warps out of previous GEMM before Apack overwrite
#pragma unroll
    for (int p = 0; p < 4; p++) {
#pragma unroll
        for (int mt = 0; mt < 2; mt++) {
            uint32_t hi[4], lo[4];
#pragma unroll
            for (int e = 0; e < 2; e++) {
                int nt = 2 * p + e;
                int cg = wn * 64 + nt * 8 + t * 2;
                float2 bb = *(const float2*)(bv + cg);
                float v0 = gelu(c[mt][nt][0] + bb.x);
                float v1 = gelu(c[mt][nt][1] + bb.y);
                float v2 = gelu(c[mt][nt][2] + bb.x);
                float v3 = gelu(c[mt][nt][3] + bb.y);
                split2(v0, v1, hi[e * 2], lo[e * 2]);
                split2(v2, v3, hi[e * 2 + 1], lo[e * 2 + 1]);
            }
            *(uint4*)(apw + p * 2048 + mt * 128)          = make_uint4(hi[0], hi[1], hi[2], hi[3]);
            *(uint4*)(apw + p * 2048 + mt * 128 + APL_PL) = make_uint4(lo[0], lo[1], lo[2], lo[3]);
        }
    }
}

__global__ void __launch_bounds__(NTHR, 2)
stab_hmma(const float* __restrict__ meas, const float* __restrict__ event,
          const float* __restrict__ leak, const float* __restrict__ event_leak,
          const int* __restrict__ stab_ids, const int* __restrict__ cycle_ids,
          const float* __restrict__ w_meas, const float* __restrict__ b_meas,
          const float* __restrict__ w_event, const float* __restrict__ b_event,
          const float* __restrict__ w_leak, const float* __restrict__ b_leak,
          const float* __restrict__ w_el, const float* __restrict__ b_el,
          const float* __restrict__ stab_table, const float* __restrict__ cycle_table,
          const float* __restrict__ g1, const float* __restrict__ be1,
          const float* __restrict__ b11, const float* __restrict__ b12,
          const float* __restrict__ g2, const float* __restrict__ be2,
          const float* __restrict__ b21, const float* __restrict__ b22,
          float* __restrict__ out) {
    extern __shared__ char smem[];
    const uint32_t sb = s2u(smem);
    float*  prm  = (float*)(smem + PRM_OFF);
    float*  psum = (float*)(smem + PS_OFF);
    float*  psq  = (float*)(smem + PSQ_OFF);
    float*  apf  = (float*)(smem + AP_OFF);   // embed-param staging (before Apack is used)

    const int tid = threadIdx.x, w = tid >> 5, lane = tid & 31;
    const int wn = w & 3, wm = w >> 2;        // wn 0..3, wm 0..1
    const int t = lane & 3, g = lane >> 2;
    const int rowbase = wm * 32 + g;
    const int base = blockIdx.x * 64;

    // 4 residual rows per thread: idx(mt,h) = rowbase + mt*16 + h*8
    float* xr[2][2];
#pragma unroll
    for (int mt = 0; mt < 2; mt++)
#pragma unroll
        for (int h = 0; h < 2; h++)
            xr[mt][h] = out + (size_t)(base + rowbase + mt * 16 + h * 8) * 256;

    // A cell addresses
    const char* apr = smem + AP_OFF + t * 512 + wm * 256 + g * 16;          // + kt*2048 + mt*128
    char*       apw = smem + AP_OFF + wn * 8192 + t * 512 + wm * 256 + g * 16; // + p*2048 + mt*128

    {   // permanent params (8KB) + embed staging in Apack region (5KB)
        const float* P[8] = {g1, be1, b11, b12, g2, be2, b21, b22};
        for (int i = tid; i < 8 * 256; i += NTHR) prm[i] = P[i >> 8][i & 255];
        const float* Q[4] = {w_meas, w_event, w_leak, w_el};
        for (int i = tid; i < 4 * 256; i += NTHR) apf[256 + i] = Q[i >> 8][i & 255];
        for (int i = tid; i < 256; i += NTHR)
            apf[i] = b_meas[i] + b_event[i] + b_leak[i] + b_el[i];
    }
    __syncthreads();

    float c[2][8][4];

    // ---- embed (values land directly in C/A-fragment layout); x -> out ----
#pragma unroll
    for (int mt = 0; mt < 2; mt++) {
        int r0 = base + rowbase + mt * 16;
        int r1 = r0 + 8;
        float me0 = meas[r0], me1 = meas[r1];
        float ev0 = event[r0], ev1 = event[r1];
        float lk0 = leak[r0], lk1 = leak[r1];
        float el0 = event_leak[r0], el1 = event_leak[r1];
        const float* st0 = stab_table + (size_t)stab_ids[r0] * 256;
        const float* st1 = stab_table + (size_t)stab_ids[r1] * 256;
        const float* cy0 = cycle_table + (size_t)cycle_ids[r0] * 256;
        const float* cy1 = cycle_table + (size_t)cycle_ids[r1] * 256;
#pragma unroll
        for (int nt = 0; nt < 8; nt++) {
            int cg = wn * 64 + nt * 8 + t * 2;
            float2 bc  = *(const float2*)(apf + 0 * 256 + cg);
            float2 wmv = *(const float2*)(apf + 1 * 256 + cg);
            float2 wev = *(const float2*)(apf + 2 * 256 + cg);
            float2 wlv = *(const float2*)(apf + 3 * 256 + cg);
            float2 wzv = *(const float2*)(apf + 4 * 256 + cg);
            float2 s0 = *(const float2*)(st0 + cg), s1 = *(const float2*)(st1 + cg);
            float2 q0 = *(const float2*)(cy0 + cg), q1 = *(const float2*)(cy1 + cg);
            c[mt][nt][0] = bc.x + me0 * wmv.x + ev0 * wev.x + lk0 * wlv.x + el0 * wzv.x + s0.x + q0.x;
            c[mt][nt][1] = bc.y + me0 * wmv.y + ev0 * wev.y + lk0 * wlv.y + el0 * wzv.y + s0.y + q0.y;
            c[mt][nt][2] = bc.x + me1 * wmv.x + ev1 * wev.x + lk1 * wlv.x + el1 * wzv.x + s1.x + q1.x;
            c[mt][nt][3] = bc.y + me1 * wmv.y + ev1 * wev.y + lk1 * wlv.y + el1 * wzv.y + s1.y + q1.y;
            *(float2*)(xr[mt][0] + cg) = make_float2(c[mt][nt][0], c[mt][nt][1]);
            *(float2*)(xr[mt][1] + cg) = make_float2(c[mt][nt][2], c[mt][nt][3]);
        }
    }

    // prefetch GEMM1 chunk0 under the LN1 epilogue
    prefetch_c0(sb, &g_wpack[0][0][0], tid);

    float mu[2][2], rs[2][2];
    ln_stats(c, psum, psq, wn, rowbase, t, mu, rs);   // syncthreads inside
    norm_split(c, prm + 0 * 256, prm + 1 * 256, mu, rs, apw, wn, t);

    // GEMM1 ; GELU(+b11)
    gemm256(smem, sb, &g_wpack[0][0][0], c, tid, wn, apr);
    prefetch_c0(sb, &g_wpack[1][0][0], tid);
    gelu_split(c, prm + 2 * 256, apw, wn, t);

    // GEMM2 ; x += D + b12 ; LN2
    gemm256(smem, sb, &g_wpack[1][0][0], c, tid, wn, apr);
    prefetch_c0(sb, &g_wpack[2][0][0], tid);
#pragma unroll
    for (int mt = 0; mt < 2; mt++)
#pragma unroll
        for (int nt = 0; nt < 8; nt++) {
            int cg = wn * 64 + nt * 8 + t * 2;
            float2 bb = *(const float2*)(prm + 3 * 256 + cg);
            float2 x0 = *(const float2*)(xr[mt][0] + cg);
            float2 x1 = *(const float2*)(xr[mt][1] + cg);
            c[mt][nt][0] = x0.x + c[mt][nt][0] + bb.x;
            c[mt][nt][1] = x0.y + c[mt][nt][1] + bb.y;
            c[mt][nt][2] = x1.x + c[mt][nt][2] + bb.x;
            c[mt][nt][3] = x1.y + c[mt][nt][3] + bb.y;
            *(float2*)(xr[mt][0] + cg) = make_float2(c[mt][nt][0], c[mt][nt][1]);
            *(float2*)(xr[mt][1] + cg) = make_float2(c[mt][nt][2], c[mt][nt][3]);
        }
    ln_stats(c, psum, psq, wn, rowbase, t, mu, rs);
    norm_split(c, prm + 4 * 256, prm + 5 * 256, mu, rs, apw, wn, t);

    // GEMM3 ; GELU(+b21)
    gemm256(smem, sb, &g_wpack[2][0][0], c, tid, wn, apr);
    prefetch_c0(sb, &g_wpack[3][0][0], tid);
    gelu_split(c, prm + 6 * 256, apw, wn, t);

    // GEMM4 ; out = x + D + b22   (x read from out, final overwrites in place)
    gemm256(smem, sb, &g_wpack[3][0][0], c, tid, wn, apr);
#pragma unroll
    for (int mt = 0; mt < 2; mt++)
#pragma unroll
        for (int nt = 0; nt < 8; nt++) {
            int cg = wn * 64 + nt * 8 + t * 2;
            float2 bb = *(const float2*)(prm + 7 * 256 + cg);
            float2 x0 = *(const float2*)(xr[mt][0] + cg);
            float2 x1 = *(const float2*)(xr[mt][1] + cg);
            *(float2*)(xr[mt][0] + cg) =
                make_float2(x0.x + c[mt][nt][0] + bb.x, x0.y + c[mt][nt][1] + bb.y);
            *(float2*)(xr[mt][1] + cg) =
                make_float2(x1.x + c[mt][nt][2] + bb.x, x1.y + c[mt][nt][3] + bb.y);
        }
}

extern "C" void kernel_launch(void* const* d_in, const int* in_sizes, int n_in,
                              void* d_out, int out_size) {
    const float* meas       = (const float*)d_in[0];
    const float* event      = (const float*)d_in[1];
    const float* leak       = (const float*)d_in[2];
    const float* event_leak = (const float*)d_in[3];
    const int*   stab_ids   = (const int*)d_in[4];
    const int*   cycle_ids  = (const int*)d_in[5];
    const float* w_meas  = (const float*)d_in[6];
    const float* b_meas  = (const float*)d_in[7];
    const float* w_event = (const float*)d_in[8];
    const float* b_event = (const float*)d_in[9];
    const float* w_leak  = (const float*)d_in[10];
    const float* b_leak  = (const float*)d_in[11];
    const float* w_el    = (const float*)d_in[12];
    const float* b_el    = (const float*)d_in[13];
    const float* stab_table  = (const float*)d_in[14];
    const float* cycle_table = (const float*)d_in[15];
    const float* g1  = (const float*)d_in[16];
    const float* be1 = (const float*)d_in[17];
    const float* W11 = (const float*)d_in[18];
    const float* b11 = (const float*)d_in[19];
    const float* W12 = (const float*)d_in[20];
    const float* b12 = (const float*)d_in[21];
    const float* g2  = (const float*)d_in[22];
    const float* be2 = (const float*)d_in[23];
    const float* W21 = (const float*)d_in[24];
    const float* b21 = (const float*)d_in[25];
    const float* W22 = (const float*)d_in[26];
    const float* b22 = (const float*)d_in[27];

    const int n_tokens = in_sizes[0];
    const int nblocks  = n_tokens / 64;    // 4096

    prep_w<<<32, 256>>>(W11, W12, W21, W22);

    cudaFuncSetAttribute(stab_hmma,
                         cudaFuncAttributeMaxDynamicSharedMemorySize, SMEM_TOTAL);
    stab_hmma<<<nblocks, NTHR, SMEM_TOTAL>>>(
        meas, event, leak, event_leak, stab_ids, cycle_ids,
        w_meas, b_meas, w_event, b_event, w_leak, b_leak, w_el, b_el,
        stab_table, cycle_table,
        g1, be1, b11, b12, g2, be2, b21, b22,
        (float*)d_out);
}

// round 14
// speedup vs baseline: 1.2483x; 1.2483x over previous
#include <cuda_runtime.h>
#include <cuda_fp16.h>
#include <math.h>
#include <stdint.h>

#define EPS   1e-5f
#define NTHR  256

// ---- SMEM layout (bytes) ----
#define AP_OFF   0                          // Apack hi plane 32KB (embed params staged here first)
#define APL_PL   32768                      // lo plane offset
#define WB0_OFF  65536                      // 16KB chunk buf
#define WB1_OFF  81920                      // 16KB chunk buf
#define PRM_OFF  98304                      // 8 vec * 1KB
#define PS_OFF   106496                     // 1KB (4*64 floats)
#define PSQ_OFF  107520                     // 1KB
#define SMEM_TOTAL 108544                   // 106KB -> 2 CTAs/SM

// prepped fp16 weights: [gemm][chunk 8][4096 u32]; chunk = 2 kt (16KB)
__device__ __align__(16) uint32_t g_wpack[4][8][4096];

__device__ __forceinline__ uint32_t s2u(const void* p) {
    uint32_t a;
    asm("{ .reg .u64 t; cvta.to.shared.u64 t, %1; cvt.u32.u64 %0, t; }" : "=r"(a) : "l"(p));
    return a;
}

__device__ __forceinline__ void hmma(float* c, const uint32_t* a, uint32_t b0, uint32_t b1) {
    asm volatile("mma.sync.aligned.m16n8k16.row.col.f32.f16.f16.f32 "
        "{%0,%1,%2,%3}, {%4,%5,%6,%7}, {%8,%9}, {%0,%1,%2,%3};"
        : "+f"(c[0]), "+f"(c[1]), "+f"(c[2]), "+f"(c[3])
        : "r"(a[0]), "r"(a[1]), "r"(a[2]), "r"(a[3]), "r"(b0), "r"(b1));
}

__device__ __forceinline__ void cp16(uint32_t dst, const void* src) {
    uint64_t gp = __cvta_generic_to_global(src);
    asm volatile("cp.async.cg.shared.global [%0], [%1], 16;" :: "r"(dst), "l"(gp));
}
#define CP_COMMIT() asm volatile("cp.async.commit_group;" ::: "memory")
#define CP_WAIT0()  asm volatile("cp.async.wait_group 0;" ::: "memory")

// 2-term fp16 split of activations
__device__ __forceinline__ void split2(float v0, float v1, uint32_t& hi, uint32_t& lo) {
    __half2 h = __floats2half2_rn(v0, v1);
    float r0 = v0 - __half2float(__low2half(h));
    float r1 = v1 - __half2float(__high2half(h));
    __half2 l = __floats2half2_rn(r0, r1);
    hi = *reinterpret_cast<uint32_t*>(&h);
    lo = *reinterpret_cast<uint32_t*>(&l);
}

__device__ __forceinline__ float gelu(float x) {
    return 0.5f * x * (1.0f + erff(x * 0.70710678118654752f));
}

// ---- prep: pack W (fp32 [k][n]) -> fragment-ready single-fp16 chunks ----
__global__ void prep_w(const float* __restrict__ W11, const float* __restrict__ W12,
                       const float* __restrict__ W21, const float* __restrict__ W22) {
    const float* Ws[4] = {W11, W12, W21, W22};
    int gi = blockIdx.x >> 3, cc = blockIdx.x & 7;
    const float* W = Ws[gi];
    for (int i = threadIdx.x; i < 4096; i += blockDim.x) {
        int kt_local = i >> 11;
        int j = i & 2047;
        int ntp = j >> 7;
        int lane = (j >> 2) & 31;
        int comp = j & 3;
        int nt = ntp * 2 + (comp >> 1);
        int which = comp & 1;
        int t = lane & 3, gg = lane >> 2;
        int n = nt * 8 + gg;
        int k = (cc * 2 + kt_local) * 16 + t * 2 + which * 8;
        __half2 r = __floats2half2_rn(W[k * 256 + n], W[(k + 1) * 256 + n]);
        g_wpack[gi][cc][i] = *reinterpret_cast<uint32_t*>(&r);
    }
}

// chunk-0 prefetch (into WB0) — overlaps preceding epilogue
__device__ __forceinline__ void prefetch_c0(uint32_t sb, const uint32_t* wsrc, int tid) {
    uint32_t d = sb + WB0_OFF + tid * 16;
    const char* s = (const char*)wsrc + tid * 16;
#pragma unroll
    for (int i = 0; i < 4; i++) cp16(d + i * 4096, s + i * 4096);
    CP_COMMIT();
}

// ---- one fused 64x256x256 GEMM (2-term fp16); chunk0 already in flight ----
// A cell layout (conflict-free): offset = kt*2048 + tile*512 + lane*16 (lane = g*4+t)
// warp grid: wm in {0,1} covers tiles {2wm, 2wm+1}; wn in {0..3} covers nt 0..7
__device__ __forceinline__ void gemm256(const char* smem, uint32_t sb, const uint32_t* wsrc,
                                        float (&c)[2][8][4], int tid, int wn,
                                        const char* apr) {
#pragma unroll
    for (int mt = 0; mt < 2; mt++)
#pragma unroll
        for (int nt = 0; nt < 8; nt++)
#pragma unroll
            for (int q = 0; q < 4; q++) c[mt][nt][q] = 0.f;

    const uint32_t dst0 = sb + WB0_OFF + tid * 16;
    const uint32_t dst1 = sb + WB1_OFF + tid * 16;
    const char* src = (const char*)wsrc + tid * 16;
    const char* wb0 = smem + WB0_OFF + wn * 2048 + (tid & 31) * 16;
    const char* wb1 = smem + WB1_OFF + wn * 2048 + (tid & 31) * 16;

#pragma unroll
    for (int ch = 0; ch < 8; ch++) {
        CP_WAIT0();
        __syncthreads();
        if (ch + 1 < 8) {
            uint32_t d = ((ch + 1) & 1) ? dst1 : dst0;
            const char* s = src + (ch + 1) * 16384;
#pragma unroll
            for (int i = 0; i < 4; i++) cp16(d + i * 4096, s + i * 4096);
            CP_COMMIT();
        }
        const char* wb = (ch & 1) ? wb1 : wb0;
#pragma unroll
        for (int kl = 0; kl < 2; kl++) {
            const int kt = ch * 2 + kl;
            const char* ac = apr + kt * 2048;
            uint4 ah0 = *(const uint4*)(ac);
            uint4 ah1 = *(const uint4*)(ac + 512);
            uint4 al0 = *(const uint4*)(ac + APL_PL);
            uint4 al1 = *(const uint4*)(ac + APL_PL + 512);
            uint32_t ahi[2][4] = {{ah0.x, ah0.y, ah0.z, ah0.w}, {ah1.x, ah1.y, ah1.z, ah1.w}};
            uint32_t alo[2][4] = {{al0.x, al0.y, al0.z, al0.w}, {al1.x, al1.y, al1.z, al1.w}};
            const char* wbk = wb + kl * 8192;
#pragma unroll
            for (int jj = 0; jj < 4; jj++) {
                uint4 b = *(const uint4*)(wbk + jj * 512);
#pragma unroll
                for (int mt = 0; mt < 2; mt++) {
                    hmma(c[mt][jj * 2],     ahi[mt], b.x, b.y);
                    hmma(c[mt][jj * 2],     alo[mt], b.x, b.y);
                    hmma(c[mt][jj * 2 + 1], ahi[mt], b.z, b.w);
                    hmma(c[mt][jj * 2 + 1], alo[mt], b.z, b.w);
                }
            }
        }
    }
}

// rows per thread: idx(mt,h) = wm*32 + mt*16 + h*8 + g
__device__ __forceinline__ void ln_stats(float (&c)[2][8][4], float* psum, float* psq,
                                         int wn, int rowbase, int t,
                                         float (&mu)[2][2], float (&rs)[2][2]) {
    float s[2][2] = {{0, 0}, {0, 0}}, q[2][2] = {{0, 0}, {0, 0}};
#pragma unroll
    for (int mt = 0; mt < 2; mt++)
#pragma unroll
        for (int nt = 0; nt < 8; nt++) {
            s[mt][0] += c[mt][nt][0] + c[mt][nt][1];
            q[mt][0] += c[mt][nt][0] * c[mt][nt][0] + c[mt][nt][1] * c[mt][nt][1];
            s[mt][1] += c[mt][nt][2] + c[mt][nt][3];
            q[mt][1] += c[mt][nt][2] * c[mt][nt][2] + c[mt][nt][3] * c[mt][nt][3];
        }
#pragma unroll
    for (int mt = 0; mt < 2; mt++)
#pragma unroll
        for (int h = 0; h < 2; h++) {
            s[mt][h] += __shfl_xor_sync(~0u, s[mt][h], 1);
            s[mt][h] += __shfl_xor_sync(~0u, s[mt][h], 2);
            q[mt][h] += __shfl_xor_sync(~0u, q[mt][h], 1);
            q[mt][h] += __shfl_xor_sync(~0u, q[mt][h], 2);
        }
    if (t == 0) {
#pragma unroll
        for (int mt = 0; mt < 2; mt++)
#pragma unroll
            for (int h = 0; h < 2; h++) {
                int idx = rowbase + mt * 16 + h * 8;
                psum[wn * 64 + idx] = s[mt][h];
                psq[wn * 64 + idx]  = q[mt][h];
            }
    }
    __syncthreads();
#pragma unroll
    for (int mt = 0; mt < 2; mt++)
#pragma unroll
        for (int h = 0; h < 2; h++) {
            int idx = rowbase + mt * 16 + h * 8;
            float ts = psum[idx] + psum[64 + idx] + psum[128 + idx] + psum[192 + idx];
            float tq = psq[idx] + psq[64 + idx] + psq[128 + idx] + psq[192 + idx];
            float m = ts * (1.f / 256.f);
            mu[mt][h] = m;
            rs[mt][h] = rsqrtf(tq * (1.f / 256.f) - m * m + EPS);
        }
}

// writer: cell(kt=wn*4+p, tile=2wm+mt, lane) at apw + p*2048 + mt*512 (hi), +APL_PL (lo)
__device__ __forceinline__ void norm_split(float (&c)[2][8][4], const float* gv, const float* bv,
                                           float (&mu)[2][2], float (&rs)[2][2],
                                           char* apw, int wn, int t) {
#pragma unroll
    for (int p = 0; p < 4; p++) {
#pragma unroll
        for (int mt = 0; mt < 2; mt++) {
            uint32_t hi[4], lo[4];
#pragma unroll
            for (int e = 0; e < 2; e++) {
                int nt = 2 * p + e;
                int cg = wn * 64 + nt * 8 + t * 2;
                float2 gg = *(const float2*)(gv + cg);
                float2 bb = *(const float2*)(bv + cg);
                float v0 = (c[mt][nt][0] - mu[mt][0]) * rs[mt][0] * gg.x + bb.x;
                float v1 = (c[mt][nt][1] - mu[mt][0]) * rs[mt][0] * gg.y + bb.y;
                float v2 = (c[mt][nt][2] - mu[mt][1]) * rs[mt][1] * gg.x + bb.x;
                float v3 = (c[mt][nt][3] - mu[mt][1]) * rs[mt][1] * gg.y + bb.y;
                split2(v0, v1, hi[e * 2], lo[e * 2]);
                split2(v2, v3, hi[e * 2 + 1], lo[e * 2 + 1]);
            }
            *(uint4*)(apw + p * 2048 + mt * 512)          = make_uint4(hi[0], hi[1], hi[2], hi[3]);
            *(uint4*)(apw + p * 2048 + mt * 512 + APL_PL) = make_uint4(lo[0], lo[1], lo[2], lo[3]);
        }
    }
}

__device__ __forceinline__ void gelu_split(float (&c)[2][8][4], const float* bv,
                                           char* apw, int wn, int t) {
    __syncthreads();   // all warps out of previous GEMM before Apack overwrite
#pragma unroll
    for (int p = 0; p < 4; p++) {
#pragma unroll
        for (int mt = 0; mt < 2; mt++) {
            uint32_t hi[4], lo[4];
#pragma unroll
            for (int e = 0; e < 2; e++) {
                int nt = 2 * p + e;
                int cg = wn * 64 + nt * 8 + t * 2;
                float2 bb = *(const float2*)(bv + cg);
                float v0 = gelu(c[mt][nt][0] + bb.x);
                float v1 = gelu(c[mt][nt][1] + bb.y);
                float v2 = gelu(c[mt][nt][2] + bb.x);
                float v3 = gelu(c[mt][nt][3] + bb.y);
                split2(v0, v1, hi[e * 2], lo[e * 2]);
                split2(v2, v3, hi[e * 2 + 1], lo[e * 2 + 1]);
            }
            *(uint4*)(apw + p * 2048 + mt * 512)          = make_uint4(hi[0], hi[1], hi[2], hi[3]);
            *(uint4*)(apw + p * 2048 + mt * 512 + APL_PL) = make_uint4(lo[0], lo[1], lo[2], lo[3]);
        }
    }
}

__global__ void __launch_bounds__(NTHR, 2)
stab_hmma(const float* __restrict__ meas, const float* __restrict__ event,
          const float* __restrict__ leak, const float* __restrict__ event_leak,
          const int* __restrict__ stab_ids, const int* __restrict__ cycle_ids,
          const float* __restrict__ w_meas, const float* __restrict__ b_meas,
          const float* __restrict__ w_event, const float* __restrict__ b_event,
          const float* __restrict__ w_leak, const float* __restrict__ b_leak,
          const float* __restrict__ w_el, const float* __restrict__ b_el,
          const float* __restrict__ stab_table, const float* __restrict__ cycle_table,
          const float* __restrict__ g1, const float* __restrict__ be1,
          const float* __restrict__ b11, const float* __restrict__ b12,
          const float* __restrict__ g2, const float* __restrict__ be2,
          const float* __restrict__ b21, const float* __restrict__ b22,
          float* __restrict__ out) {
    extern __shared__ char smem[];
    const uint32_t sb = s2u(smem);
    float*  prm  = (float*)(smem + PRM_OFF);
    float*  psum = (float*)(smem + PS_OFF);
    float*  psq  = (float*)(smem + PSQ_OFF);
    float*  apf  = (float*)(smem + AP_OFF);   // embed-param staging (before Apack is used)

    const int tid = threadIdx.x, w = tid >> 5, lane = tid & 31;
    const int wn = w & 3, wm = w >> 2;        // wn 0..3, wm 0..1
    const int t = lane & 3, g = lane >> 2;
    const int rowbase = wm * 32 + g;
    const int base = blockIdx.x * 64;

    // 4 residual rows per thread: idx(mt,h) = rowbase + mt*16 + h*8
    float* xr[2][2];
#pragma unroll
    for (int mt = 0; mt < 2; mt++)
#pragma unroll
        for (int h = 0; h < 2; h++)
            xr[mt][h] = out + (size_t)(base + rowbase + mt * 16 + h * 8) * 256;

    // A cell addresses (conflict-free: lane-linear within each tile block)
    const char* apr = smem + AP_OFF + wm * 1024 + lane * 16;               // + kt*2048 + mt*512
    char*       apw = smem + AP_OFF + wn * 8192 + wm * 1024 + lane * 16;   // + p*2048 + mt*512

    {   // permanent params (8KB) + embed staging in Apack region (5KB)
        const float* P[8] = {g1, be1, b11, b12, g2, be2, b21, b22};
        for (int i = tid; i < 8 * 256; i += NTHR) prm[i] = P[i >> 8][i & 255];
        const float* Q[4] = {w_meas, w_event, w_leak, w_el};
        for (int i = tid; i < 4 * 256; i += NTHR) apf[256 + i] = Q[i >> 8][i & 255];
        for (int i = tid; i < 256; i += NTHR)
            apf[i] = b_meas[i] + b_event[i] + b_leak[i] + b_el[i];
    }
    __syncthreads();

    float c[2][8][4];

    // ---- embed (values land directly in C/A-fragment layout); x -> out ----
#pragma unroll
    for (int mt = 0; mt < 2; mt++) {
        int r0 = base + rowbase + mt * 16;
        int r1 = r0 + 8;
        float me0 = meas[r0], me1 = meas[r1];
        float ev0 = event[r0], ev1 = event[r1];
        float lk0 = leak[r0], lk1 = leak[r1];
        float el0 = event_leak[r0], el1 = event_leak[r1];
        const float* st0 = stab_table + (size_t)stab_ids[r0] * 256;
        const float* st1 = stab_table + (size_t)stab_ids[r1] * 256;
        const float* cy0 = cycle_table + (size_t)cycle_ids[r0] * 256;
        const float* cy1 = cycle_table + (size_t)cycle_ids[r1] * 256;
#pragma unroll
        for (int nt = 0; nt < 8; nt++) {
            int cg = wn * 64 + nt * 8 + t * 2;
            float2 bc  = *(const float2*)(apf + 0 * 256 + cg);
            float2 wmv = *(const float2*)(apf + 1 * 256 + cg);
            float2 wev = *(const float2*)(apf + 2 * 256 + cg);
            float2 wlv = *(const float2*)(apf + 3 * 256 + cg);
            float2 wzv = *(const float2*)(apf + 4 * 256 + cg);
            float2 s0 = *(const float2*)(st0 + cg), s1 = *(const float2*)(st1 + cg);
            float2 q0 = *(const float2*)(cy0 + cg), q1 = *(const float2*)(cy1 + cg);
            c[mt][nt][0] = bc.x + me0 * wmv.x + ev0 * wev.x + lk0 * wlv.x + el0 * wzv.x + s0.x + q0.x;
            c[mt][nt][1] = bc.y + me0 * wmv.y + ev0 * wev.y + lk0 * wlv.y + el0 * wzv.y + s0.y + q0.y;
            c[mt][nt][2] = bc.x + me1 * wmv.x + ev1 * wev.x + lk1 * wlv.x + el1 * wzv.x + s1.x + q1.x;
            c[mt][nt][3] = bc.y + me1 * wmv.y + ev1 * wev.y + lk1 * wlv.y + el1 * wzv.y + s1.y + q1.y;
            *(float2*)(xr[mt][0] + cg) = make_float2(c[mt][nt][0], c[mt][nt][1]);
            *(float2*)(xr[mt][1] + cg) = make_float2(c[mt][nt][2], c[mt][nt][3]);
        }
    }

    // prefetch GEMM1 chunk0 under the LN1 epilogue
    prefetch_c0(sb, &g_wpack[0][0][0], tid);

    float mu[2][2], rs[2][2];
    ln_stats(c, psum, psq, wn, rowbase, t, mu, rs);   // syncthreads inside
    norm_split(c, prm + 0 * 256, prm + 1 * 256, mu, rs, apw, wn, t);

    // GEMM1 ; GELU(+b11)
    gemm256(smem, sb, &g_wpack[0][0][0], c, tid, wn, apr);
    prefetch_c0(sb, &g_wpack[1][0][0], tid);
    gelu_split(c, prm + 2 * 256, apw, wn, t);

    // GEMM2 ; x += D + b12 ; LN2
    gemm256(smem, sb, &g_wpack[1][0][0], c, tid, wn, apr);
    prefetch_c0(sb, &g_wpack[2][0][0], tid);
#pragma unroll
    for (int mt = 0; mt < 2; mt++)
#pragma unroll
        for (int nt = 0; nt < 8; nt++) {
            int cg = wn * 64 + nt * 8 + t * 2;
            float2 bb = *(const float2*)(prm + 3 * 256 + cg);
            float2 x0 = *(const float2*)(xr[mt][0] + cg);
            float2 x1 = *(const float2*)(xr[mt][1] + cg);
            c[mt][nt][0] = x0.x + c[mt][nt][0] + bb.x;
            c[mt][nt][1] = x0.y + c[mt][nt][1] + bb.y;
            c[mt][nt][2] = x1.x + c[mt][nt][2] + bb.x;
            c[mt][nt][3] = x1.y + c[mt][nt][3] + bb.y;
            *(float2*)(xr[mt][0] + cg) = make_float2(c[mt][nt][0], c[mt][nt][1]);
            *(float2*)(xr[mt][1] + cg) = make_float2(c[mt][nt][2], c[mt][nt][3]);
        }
    ln_stats(c, psum, psq, wn, rowbase, t, mu, rs);
    norm_split(c, prm + 4 * 256, prm + 5 * 256, mu, rs, apw, wn, t);

    // GEMM3 ; GELU(+b21)
    gemm256(smem, sb, &g_wpack[2][0][0], c, tid, wn, apr);
    prefetch_c0(sb, &g_wpack[3][0][0], tid);
    gelu_split(c, prm + 6 * 256, apw, wn, t);

    // GEMM4 ; out = x + D + b22   (x read from out, final overwrites in place)
    gemm256(smem, sb, &g_wpack[3][0][0], c, tid, wn, apr);
#pragma unroll
    for (int mt = 0; mt < 2; mt++)
#pragma unroll
        for (int nt = 0; nt < 8; nt++) {
            int cg = wn * 64 + nt * 8 + t * 2;
            float2 bb = *(const float2*)(prm + 7 * 256 + cg);
            float2 x0 = *(const float2*)(xr[mt][0] + cg);
            float2 x1 = *(const float2*)(xr[mt][1] + cg);
            *(float2*)(xr[mt][0] + cg) =
                make_float2(x0.x + c[mt][nt][0] + bb.x, x0.y + c[mt][nt][1] + bb.y);
            *(float2*)(xr[mt][1] + cg) =
                make_float2(x1.x + c[mt][nt][2] + bb.x, x1.y + c[mt][nt][3] + bb.y);
        }
}

extern "C" void kernel_launch(void* const* d_in, const int* in_sizes, int n_in,
                              void* d_out, int out_size) {
    const float* meas       = (const float*)d_in[0];
    const float* event      = (const float*)d_in[1];
    const float* leak       = (const float*)d_in[2];
    const float* event_leak = (const float*)d_in[3];
    const int*   stab_ids   = (const int*)d_in[4];
    const int*   cycle_ids  = (const int*)d_in[5];
    const float* w_meas  = (const float*)d_in[6];
    const float* b_meas  = (const float*)d_in[7];
    const float* w_event = (const float*)d_in[8];
    const float* b_event = (const float*)d_in[9];
    const float* w_leak  = (const float*)d_in[10];
    const float* b_leak  = (const float*)d_in[11];
    const float* w_el    = (const float*)d_in[12];
    const float* b_el    = (const float*)d_in[13];
    const float* stab_table  = (const float*)d_in[14];
    const float* cycle_table = (const float*)d_in[15];
    const float* g1  = (const float*)d_in[16];
    const float* be1 = (const float*)d_in[17];
    const float* W11 = (const float*)d_in[18];
    const float* b11 = (const float*)d_in[19];
    const float* W12 = (const float*)d_in[20];
    const float* b12 = (const float*)d_in[21];
    const float* g2  = (const float*)d_in[22];
    const float* be2 = (const float*)d_in[23];
    const float* W21 = (const float*)d_in[24];
    const float* b21 = (const float*)d_in[25];
    const float* W22 = (const float*)d_in[26];
    const float* b22 = (const float*)d_in[27];

    const int n_tokens = in_sizes[0];
    const int nblocks  = n_tokens / 64;    // 4096

    prep_w<<<32, 256>>>(W11, W12, W21, W22);

    cudaFuncSetAttribute(stab_hmma,
                         cudaFuncAttributeMaxDynamicSharedMemorySize, SMEM_TOTAL);
    stab_hmma<<<nblocks, NTHR, SMEM_TOTAL>>>(
        meas, event, leak, event_leak, stab_ids, cycle_ids,
        w_meas, b_meas, w_event, b_event, w_leak, b_leak, w_el, b_el,
        stab_table, cycle_table,
        g1, be1, b11, b12, g2, be2, b21, b22,
        (float*)d_out);
}

// round 15
// speedup vs baseline: 1.6437x; 1.3167x over previous
#include <cuda_runtime.h>
#include <cuda_fp16.h>
#include <math.h>
#include <stdint.h>

#define EPS   1e-5f
#define NTHR  256

// ---- SMEM layout (bytes) ----
#define AP_OFF   0                          // Apack (single fp16 plane) 32KB; embed params staged here first
#define WB0_OFF  32768                      // 16KB chunk buf
#define WB1_OFF  49152                      // 16KB chunk buf
#define PRM_OFF  65536                      // 8 vec * 1KB
#define PS_OFF   73728                      // 1KB (4*64 floats)
#define PSQ_OFF  74752                      // 1KB
#define SMEM_TOTAL 75776                    // 74KB -> 2 CTAs/SM

// prepped fp16 weights: [gemm][chunk 8][4096 u32]; chunk = 2 kt (16KB)
__device__ __align__(16) uint32_t g_wpack[4][8][4096];

__device__ __forceinline__ uint32_t s2u(const void* p) {
    uint32_t a;
    asm("{ .reg .u64 t; cvta.to.shared.u64 t, %1; cvt.u32.u64 %0, t; }" : "=r"(a) : "l"(p));
    return a;
}

__device__ __forceinline__ void hmma(float* c, const uint32_t* a, uint32_t b0, uint32_t b1) {
    asm volatile("mma.sync.aligned.m16n8k16.row.col.f32.f16.f16.f32 "
        "{%0,%1,%2,%3}, {%4,%5,%6,%7}, {%8,%9}, {%0,%1,%2,%3};"
        : "+f"(c[0]), "+f"(c[1]), "+f"(c[2]), "+f"(c[3])
        : "r"(a[0]), "r"(a[1]), "r"(a[2]), "r"(a[3]), "r"(b0), "r"(b1));
}

__device__ __forceinline__ void cp16(uint32_t dst, const void* src) {
    uint64_t gp = __cvta_generic_to_global(src);
    asm volatile("cp.async.cg.shared.global [%0], [%1], 16;" :: "r"(dst), "l"(gp));
}
#define CP_COMMIT() asm volatile("cp.async.commit_group;" ::: "memory")
#define CP_WAIT0()  asm volatile("cp.async.wait_group 0;" ::: "memory")

__device__ __forceinline__ uint32_t pack2(float v0, float v1) {
    __half2 h = __floats2half2_rn(v0, v1);
    return *reinterpret_cast<uint32_t*>(&h);
}

__device__ __forceinline__ float gelu(float x) {
    return 0.5f * x * (1.0f + erff(x * 0.70710678118654752f));
}

// ---- prep: pack W (fp32 [k][n]) -> fragment-ready single-fp16 chunks ----
__global__ void prep_w(const float* __restrict__ W11, const float* __restrict__ W12,
                       const float* __restrict__ W21, const float* __restrict__ W22) {
    const float* Ws[4] = {W11, W12, W21, W22};
    int gi = blockIdx.x >> 3, cc = blockIdx.x & 7;
    const float* W = Ws[gi];
    for (int i = threadIdx.x; i < 4096; i += blockDim.x) {
        int kt_local = i >> 11;
        int j = i & 2047;
        int ntp = j >> 7;
        int lane = (j >> 2) & 31;
        int comp = j & 3;
        int nt = ntp * 2 + (comp >> 1);
        int which = comp & 1;
        int t = lane & 3, gg = lane >> 2;
        int n = nt * 8 + gg;
        int k = (cc * 2 + kt_local) * 16 + t * 2 + which * 8;
        __half2 r = __floats2half2_rn(W[k * 256 + n], W[(k + 1) * 256 + n]);
        g_wpack[gi][cc][i] = *reinterpret_cast<uint32_t*>(&r);
    }
}

// chunk-0 prefetch (into WB0) — overlaps preceding epilogue
__device__ __forceinline__ void prefetch_c0(uint32_t sb, const uint32_t* wsrc, int tid) {
    uint32_t d = sb + WB0_OFF + tid * 16;
    const char* s = (const char*)wsrc + tid * 16;
#pragma unroll
    for (int i = 0; i < 4; i++) cp16(d + i * 4096, s + i * 4096);
    CP_COMMIT();
}

// ---- one fused 64x256x256 GEMM (single fp16 A & W); chunk0 already in flight ----
// A cell layout (conflict-free): offset = kt*2048 + tile*512 + lane*16 (lane = g*4+t)
// warp grid: wm in {0,1} covers tiles {2wm, 2wm+1}; wn in {0..3} covers nt 0..7
__device__ __forceinline__ void gemm256(const char* smem, uint32_t sb, const uint32_t* wsrc,
                                        float (&c)[2][8][4], int tid, int wn,
                                        const char* apr) {
#pragma unroll
    for (int mt = 0; mt < 2; mt++)
#pragma unroll
        for (int nt = 0; nt < 8; nt++)
#pragma unroll
            for (int q = 0; q < 4; q++) c[mt][nt][q] = 0.f;

    const uint32_t dst0 = sb + WB0_OFF + tid * 16;
    const uint32_t dst1 = sb + WB1_OFF + tid * 16;
    const char* src = (const char*)wsrc + tid * 16;
    const char* wb0 = smem + WB0_OFF + wn * 2048 + (tid & 31) * 16;
    const char* wb1 = smem + WB1_OFF + wn * 2048 + (tid & 31) * 16;

#pragma unroll
    for (int ch = 0; ch < 8; ch++) {
        CP_WAIT0();
        __syncthreads();
        if (ch + 1 < 8) {
            uint32_t d = ((ch + 1) & 1) ? dst1 : dst0;
            const char* s = src + (ch + 1) * 16384;
#pragma unroll
            for (int i = 0; i < 4; i++) cp16(d + i * 4096, s + i * 4096);
            CP_COMMIT();
        }
        const char* wb = (ch & 1) ? wb1 : wb0;
#pragma unroll
        for (int kl = 0; kl < 2; kl++) {
            const int kt = ch * 2 + kl;
            const char* ac = apr + kt * 2048;
            uint4 ah0 = *(const uint4*)(ac);
            uint4 ah1 = *(const uint4*)(ac + 512);
            uint32_t ahi[2][4] = {{ah0.x, ah0.y, ah0.z, ah0.w}, {ah1.x, ah1.y, ah1.z, ah1.w}};
            const char* wbk = wb + kl * 8192;
#pragma unroll
            for (int jj = 0; jj < 4; jj++) {
                uint4 b = *(const uint4*)(wbk + jj * 512);
#pragma unroll
                for (int mt = 0; mt < 2; mt++) {
                    hmma(c[mt][jj * 2],     ahi[mt], b.x, b.y);
                    hmma(c[mt][jj * 2 + 1], ahi[mt], b.z, b.w);
                }
            }
        }
    }
}

// rows per thread: idx(mt,h) = wm*32 + mt*16 + h*8 + g
__device__ __forceinline__ void ln_stats(float (&c)[2][8][4], float* psum, float* psq,
                                         int wn, int rowbase, int t,
                                         float (&mu)[2][2], float (&rs)[2][2]) {
    float s[2][2] = {{0, 0}, {0, 0}}, q[2][2] = {{0, 0}, {0, 0}};
#pragma unroll
    for (int mt = 0; mt < 2; mt++)
#pragma unroll
        for (int nt = 0; nt < 8; nt++) {
            s[mt][0] += c[mt][nt][0] + c[mt][nt][1];
            q[mt][0] += c[mt][nt][0] * c[mt][nt][0] + c[mt][nt][1] * c[mt][nt][1];
            s[mt][1] += c[mt][nt][2] + c[mt][nt][3];
            q[mt][1] += c[mt][nt][2] * c[mt][nt][2] + c[mt][nt][3] * c[mt][nt][3];
        }
#pragma unroll
    for (int mt = 0; mt < 2; mt++)
#pragma unroll
        for (int h = 0; h < 2; h++) {
            s[mt][h] += __shfl_xor_sync(~0u, s[mt][h], 1);
            s[mt][h] += __shfl_xor_sync(~0u, s[mt][h], 2);
            q[mt][h] += __shfl_xor_sync(~0u, q[mt][h], 1);
            q[mt][h] += __shfl_xor_sync(~0u, q[mt][h], 2);
        }
    if (t == 0) {
#pragma unroll
        for (int mt = 0; mt < 2; mt++)
#pragma unroll
            for (int h = 0; h < 2; h++) {
                int idx = rowbase + mt * 16 + h * 8;
                psum[wn * 64 + idx] = s[mt][h];
                psq[wn * 64 + idx]  = q[mt][h];
            }
    }
    __syncthreads();
#pragma unroll
    for (int mt = 0; mt < 2; mt++)
#pragma unroll
        for (int h = 0; h < 2; h++) {
            int idx = rowbase + mt * 16 + h * 8;
            float ts = psum[idx] + psum[64 + idx] + psum[128 + idx] + psum[192 + idx];
            float tq = psq[idx] + psq[64 + idx] + psq[128 + idx] + psq[192 + idx];
            float m = ts * (1.f / 256.f);
            mu[mt][h] = m;
            rs[mt][h] = rsqrtf(tq * (1.f / 256.f) - m * m + EPS);
        }
}

// writer: cell(kt=wn*4+p, tile=2wm+mt, lane) at apw + p*2048 + mt*512
__device__ __forceinline__ void norm_split(float (&c)[2][8][4], const float* gv, const float* bv,
                                           float (&mu)[2][2], float (&rs)[2][2],
                                           char* apw, int wn, int t) {
#pragma unroll
    for (int p = 0; p < 4; p++) {
#pragma unroll
        for (int mt = 0; mt < 2; mt++) {
            uint32_t hi[4];
#pragma unroll
            for (int e = 0; e < 2; e++) {
                int nt = 2 * p + e;
                int cg = wn * 64 + nt * 8 + t * 2;
                float2 gg = *(const float2*)(gv + cg);
                float2 bb = *(const float2*)(bv + cg);
                float v0 = (c[mt][nt][0] - mu[mt][0]) * rs[mt][0] * gg.x + bb.x;
                float v1 = (c[mt][nt][1] - mu[mt][0]) * rs[mt][0] * gg.y + bb.y;
                float v2 = (c[mt][nt][2] - mu[mt][1]) * rs[mt][1] * gg.x + bb.x;
                float v3 = (c[mt][nt][3] - mu[mt][1]) * rs[mt][1] * gg.y + bb.y;
                hi[e * 2]     = pack2(v0, v1);
                hi[e * 2 + 1] = pack2(v2, v3);
            }
            *(uint4*)(apw + p * 2048 + mt * 512) = make_uint4(hi[0], hi[1], hi[2], hi[3]);
        }
    }
}

__device__ __forceinline__ void gelu_split(float (&c)[2][8][4], const float* bv,
                                           char* apw, int wn, int t) {
    __syncthreads();   // all warps out of previous GEMM before Apack overwrite
#pragma unroll
    for (int p = 0; p < 4; p++) {
#pragma unroll
        for (int mt = 0; mt < 2; mt++) {
            uint32_t hi[4];
#pragma unroll
            for (int e = 0; e < 2; e++) {
                int nt = 2 * p + e;
                int cg = wn * 64 + nt * 8 + t * 2;
                float2 bb = *(const float2*)(bv + cg);
                float v0 = gelu(c[mt][nt][0] + bb.x);
                float v1 = gelu(c[mt][nt][1] + bb.y);
                float v2 = gelu(c[mt][nt][2] + bb.x);
                float v3 = gelu(c[mt][nt][3] + bb.y);
                hi[e * 2]     = pack2(v0, v1);
                hi[e * 2 + 1] = pack2(v2, v3);
            }
            *(uint4*)(apw + p * 2048 + mt * 512) = make_uint4(hi[0], hi[1], hi[2], hi[3]);
        }
    }
}

__global__ void __launch_bounds__(NTHR, 2)
stab_hmma(const float* __restrict__ meas, const float* __restrict__ event,
          const float* __restrict__ leak, const float* __restrict__ event_leak,
          const int* __restrict__ stab_ids, const int* __restrict__ cycle_ids,
          const float* __restrict__ w_meas, const float* __restrict__ b_meas,
          const float* __restrict__ w_event, const float* __restrict__ b_event,
          const float* __restrict__ w_leak, const float* __restrict__ b_leak,
          const float* __restrict__ w_el, const float* __restrict__ b_el,
          const float* __restrict__ stab_table, const float* __restrict__ cycle_table,
          const float* __restrict__ g1, const float* __restrict__ be1,
          const float* __restrict__ b11, const float* __restrict__ b12,
          const float* __restrict__ g2, const float* __restrict__ be2,
          const float* __restrict__ b21, const float* __restrict__ b22,
          float* __restrict__ out) {
    extern __shared__ char smem[];
    const uint32_t sb = s2u(smem);
    float*  prm  = (float*)(smem + PRM_OFF);
    float*  psum = (float*)(smem + PS_OFF);
    float*  psq  = (float*)(smem + PSQ_OFF);
    float*  apf  = (float*)(smem + AP_OFF);   // embed-param staging (before Apack is used)

    const int tid = threadIdx.x, w = tid >> 5, lane = tid & 31;
    const int wn = w & 3, wm = w >> 2;        // wn 0..3, wm 0..1
    const int t = lane & 3, g = lane >> 2;
    const int rowbase = wm * 32 + g;
    const int base = blockIdx.x * 64;

    // 4 residual rows per thread: idx(mt,h) = rowbase + mt*16 + h*8
    float* xr[2][2];
#pragma unroll
    for (int mt = 0; mt < 2; mt++)
#pragma unroll
        for (int h = 0; h < 2; h++)
            xr[mt][h] = out + (size_t)(base + rowbase + mt * 16 + h * 8) * 256;

    // A cell addresses (conflict-free: lane-linear within each tile block)
    const char* apr = smem + AP_OFF + wm * 1024 + lane * 16;               // + kt*2048 + mt*512
    char*       apw = smem + AP_OFF + wn * 8192 + wm * 1024 + lane * 16;   // + p*2048 + mt*512

    {   // permanent params (8KB) + embed staging in Apack region (5KB)
        const float* P[8] = {g1, be1, b11, b12, g2, be2, b21, b22};
        for (int i = tid; i < 8 * 256; i += NTHR) prm[i] = P[i >> 8][i & 255];
        const float* Q[4] = {w_meas, w_event, w_leak, w_el};
        for (int i = tid; i < 4 * 256; i += NTHR) apf[256 + i] = Q[i >> 8][i & 255];
        for (int i = tid; i < 256; i += NTHR)
            apf[i] = b_meas[i] + b_event[i] + b_leak[i] + b_el[i];
    }
    __syncthreads();

    float c[2][8][4];

    // ---- embed (values land directly in C/A-fragment layout); x -> out ----
#pragma unroll
    for (int mt = 0; mt < 2; mt++) {
        int r0 = base + rowbase + mt * 16;
        int r1 = r0 + 8;
        float me0 = meas[r0], me1 = meas[r1];
        float ev0 = event[r0], ev1 = event[r1];
        float lk0 = leak[r0], lk1 = leak[r1];
        float el0 = event_leak[r0], el1 = event_leak[r1];
        const float* st0 = stab_table + (size_t)stab_ids[r0] * 256;
        const float* st1 = stab_table + (size_t)stab_ids[r1] * 256;
        const float* cy0 = cycle_table + (size_t)cycle_ids[r0] * 256;
        const float* cy1 = cycle_table + (size_t)cycle_ids[r1] * 256;
#pragma unroll
        for (int nt = 0; nt < 8; nt++) {
            int cg = wn * 64 + nt * 8 + t * 2;
            float2 bc  = *(const float2*)(apf + 0 * 256 + cg);
            float2 wmv = *(const float2*)(apf + 1 * 256 + cg);
            float2 wev = *(const float2*)(apf + 2 * 256 + cg);
            float2 wlv = *(const float2*)(apf + 3 * 256 + cg);
            float2 wzv = *(const float2*)(apf + 4 * 256 + cg);
            float2 s0 = *(const float2*)(st0 + cg), s1 = *(const float2*)(st1 + cg);
            float2 q0 = *(const float2*)(cy0 + cg), q1 = *(const float2*)(cy1 + cg);
            c[mt][nt][0] = bc.x + me0 * wmv.x + ev0 * wev.x + lk0 * wlv.x + el0 * wzv.x + s0.x + q0.x;
            c[mt][nt][1] = bc.y + me0 * wmv.y + ev0 * wev.y + lk0 * wlv.y + el0 * wzv.y + s0.y + q0.y;
            c[mt][nt][2] = bc.x + me1 * wmv.x + ev1 * wev.x + lk1 * wlv.x + el1 * wzv.x + s1.x + q1.x;
            c[mt][nt][3] = bc.y + me1 * wmv.y + ev1 * wev.y + lk1 * wlv.y + el1 * wzv.y + s1.y + q1.y;
            *(float2*)(xr[mt][0] + cg) = make_float2(c[mt][nt][0], c[mt][nt][1]);
            *(float2*)(xr[mt][1] + cg) = make_float2(c[mt][nt][2], c[mt][nt][3]);
        }
    }

    // prefetch GEMM1 chunk0 under the LN1 epilogue
    prefetch_c0(sb, &g_wpack[0][0][0], tid);

    float mu[2][2], rs[2][2];
    ln_stats(c, psum, psq, wn, rowbase, t, mu, rs);   // syncthreads inside
    norm_split(c, prm + 0 * 256, prm + 1 * 256, mu, rs, apw, wn, t);

    // GEMM1 ; GELU(+b11)
    gemm256(smem, sb, &g_wpack[0][0][0], c, tid, wn, apr);
    prefetch_c0(sb, &g_wpack[1][0][0], tid);
    gelu_split(c, prm + 2 * 256, apw, wn, t);

    // GEMM2 ; x += D + b12 ; LN2
    gemm256(smem, sb, &g_wpack[1][0][0], c, tid, wn, apr);
    prefetch_c0(sb, &g_wpack[2][0][0], tid);
#pragma unroll
    for (int mt = 0; mt < 2; mt++)
#pragma unroll
        for (int nt = 0; nt < 8; nt++) {
            int cg = wn * 64 + nt * 8 + t * 2;
            float2 bb = *(const float2*)(prm + 3 * 256 + cg);
            float2 x0 = *(const float2*)(xr[mt][0] + cg);
            float2 x1 = *(const float2*)(xr[mt][1] + cg);
            c[mt][nt][0] = x0.x + c[mt][nt][0] + bb.x;
            c[mt][nt][1] = x0.y + c[mt][nt][1] + bb.y;
            c[mt][nt][2] = x1.x + c[mt][nt][2] + bb.x;
            c[mt][nt][3] = x1.y + c[mt][nt][3] + bb.y;
            *(float2*)(xr[mt][0] + cg) = make_float2(c[mt][nt][0], c[mt][nt][1]);
            *(float2*)(xr[mt][1] + cg) = make_float2(c[mt][nt][2], c[mt][nt][3]);
        }
    ln_stats(c, psum, psq, wn, rowbase, t, mu, rs);
    norm_split(c, prm + 4 * 256, prm + 5 * 256, mu, rs, apw, wn, t);

    // GEMM3 ; GELU(+b21)
    gemm256(smem, sb, &g_wpack[2][0][0], c, tid, wn, apr);
    prefetch_c0(sb, &g_wpack[3][0][0], tid);
    gelu_split(c, prm + 6 * 256, apw, wn, t);

    // GEMM4 ; out = x + D + b22   (x read from out, final overwrites in place)
    gemm256(smem, sb, &g_wpack[3][0][0], c, tid, wn, apr);
#pragma unroll
    for (int mt = 0; mt < 2; mt++)
#pragma unroll
        for (int nt = 0; nt < 8; nt++) {
            int cg = wn * 64 + nt * 8 + t * 2;
            float2 bb = *(const float2*)(prm + 7 * 256 + cg);
            float2 x0 = *(const float2*)(xr[mt][0] + cg);
            float2 x1 = *(const float2*)(xr[mt][1] + cg);
            *(float2*)(xr[mt][0] + cg) =
                make_float2(x0.x + c[mt][nt][0] + bb.x, x0.y + c[mt][nt][1] + bb.y);
            *(float2*)(xr[mt][1] + cg) =
                make_float2(x1.x + c[mt][nt][2] + bb.x, x1.y + c[mt][nt][3] + bb.y);
        }
}

extern "C" void kernel_launch(void* const* d_in, const int* in_sizes, int n_in,
                              void* d_out, int out_size) {
    const float* meas       = (const float*)d_in[0];
    const float* event      = (const float*)d_in[1];
    const float* leak       = (const float*)d_in[2];
    const float* event_leak = (const float*)d_in[3];
    const int*   stab_ids   = (const int*)d_in[4];
    const int*   cycle_ids  = (const int*)d_in[5];
    const float* w_meas  = (const float*)d_in[6];
    const float* b_meas  = (const float*)d_in[7];
    const float* w_event = (const float*)d_in[8];
    const float* b_event = (const float*)d_in[9];
    const float* w_leak  = (const float*)d_in[10];
    const float* b_leak  = (const float*)d_in[11];
    const float* w_el    = (const float*)d_in[12];
    const float* b_el    = (const float*)d_in[13];
    const float* stab_table  = (const float*)d_in[14];
    const float* cycle_table = (const float*)d_in[15];
    const float* g1  = (const float*)d_in[16];
    const float* be1 = (const float*)d_in[17];
    const float* W11 = (const float*)d_in[18];
    const float* b11 = (const float*)d_in[19];
    const float* W12 = (const float*)d_in[20];
    const float* b12 = (const float*)d_in[21];
    const float* g2  = (const float*)d_in[22];
    const float* be2 = (const float*)d_in[23];
    const float* W21 = (const float*)d_in[24];
    const float* b21 = (const float*)d_in[25];
    const float* W22 = (const float*)d_in[26];
    const float* b22 = (const float*)d_in[27];

    const int n_tokens = in_sizes[0];
    const int nblocks  = n_tokens / 64;    // 4096

    prep_w<<<32, 256>>>(W11, W12, W21, W22);

    cudaFuncSetAttribute(stab_hmma,
                         cudaFuncAttributeMaxDynamicSharedMemorySize, SMEM_TOTAL);
    stab_hmma<<<nblocks, NTHR, SMEM_TOTAL>>>(
        meas, event, leak, event_leak, stab_ids, cycle_ids,
        w_meas, b_meas, w_event, b_event, w_leak, b_leak, w_el, b_el,
        stab_table, cycle_table,
        g1, be1, b11, b12, g2, be2, b21, b22,
        (float*)d_out);
}

// round 16
// speedup vs baseline: 2.0003x; 1.2170x over previous
#include <cuda_runtime.h>
#include <cuda_fp16.h>
#include <math.h>
#include <stdint.h>

#define EPS   1e-5f
#define NTHR  256

// ---- SMEM layout (bytes) ----
#define AP_OFF   0                          // Apack (single fp16 plane) 32KB; embed params staged here first
#define WB0_OFF  32768                      // 16KB chunk buf
#define WB1_OFF  49152                      // 16KB chunk buf
#define XS_OFF   65536                      // residual x as half2 pairs: 16 slots * 2048B = 32KB
#define PRM_OFF  98304                      // 8 vec * 1KB
#define PS_OFF   106496                     // 1KB (4*64 floats)
#define PSQ_OFF  107520                     // 1KB
#define SMEM_TOTAL 108544                   // 106KB -> 2 CTAs/SM

// prepped fp16 weights: [gemm][chunk 8][4096 u32]; chunk = 2 kt (16KB)
__device__ __align__(16) uint32_t g_wpack[4][8][4096];

__device__ __forceinline__ uint32_t s2u(const void* p) {
    uint32_t a;
    asm("{ .reg .u64 t; cvta.to.shared.u64 t, %1; cvt.u32.u64 %0, t; }" : "=r"(a) : "l"(p));
    return a;
}

__device__ __forceinline__ void hmma(float* c, const uint32_t* a, uint32_t b0, uint32_t b1) {
    asm volatile("mma.sync.aligned.m16n8k16.row.col.f32.f16.f16.f32 "
        "{%0,%1,%2,%3}, {%4,%5,%6,%7}, {%8,%9}, {%0,%1,%2,%3};"
        : "+f"(c[0]), "+f"(c[1]), "+f"(c[2]), "+f"(c[3])
        : "r"(a[0]), "r"(a[1]), "r"(a[2]), "r"(a[3]), "r"(b0), "r"(b1));
}

__device__ __forceinline__ void cp16(uint32_t dst, const void* src) {
    uint64_t gp = __cvta_generic_to_global(src);
    asm volatile("cp.async.cg.shared.global [%0], [%1], 16;" :: "r"(dst), "l"(gp));
}
#define CP_COMMIT() asm volatile("cp.async.commit_group;" ::: "memory")
#define CP_WAIT0()  asm volatile("cp.async.wait_group 0;" ::: "memory")

__device__ __forceinline__ uint32_t pack2(float v0, float v1) {
    __half2 h = __floats2half2_rn(v0, v1);
    return *reinterpret_cast<uint32_t*>(&h);
}
__device__ __forceinline__ float2 unpack2h(uint32_t u) {
    __half2 h = *reinterpret_cast<__half2*>(&u);
    return __half22float2(h);
}

__device__ __forceinline__ float gelu(float x) {
    return 0.5f * x * (1.0f + erff(x * 0.70710678118654752f));
}

// ---- prep: pack W (fp32 [k][n]) -> fragment-ready single-fp16 chunks ----
__global__ void prep_w(const float* __restrict__ W11, const float* __restrict__ W12,
                       const float* __restrict__ W21, const float* __restrict__ W22) {
    const float* Ws[4] = {W11, W12, W21, W22};
    int gi = blockIdx.x >> 3, cc = blockIdx.x & 7;
    const float* W = Ws[gi];
    for (int i = threadIdx.x; i < 4096; i += blockDim.x) {
        int kt_local = i >> 11;
        int j = i & 2047;
        int ntp = j >> 7;
        int lane = (j >> 2) & 31;
        int comp = j & 3;
        int nt = ntp * 2 + (comp >> 1);
        int which = comp & 1;
        int t = lane & 3, gg = lane >> 2;
        int n = nt * 8 + gg;
        int k = (cc * 2 + kt_local) * 16 + t * 2 + which * 8;
        __half2 r = __floats2half2_rn(W[k * 256 + n], W[(k + 1) * 256 + n]);
        g_wpack[gi][cc][i] = *reinterpret_cast<uint32_t*>(&r);
    }
}

// chunk-0 prefetch (into WB0) — overlaps preceding epilogue
__device__ __forceinline__ void prefetch_c0(uint32_t sb, const uint32_t* wsrc, int tid) {
    uint32_t d = sb + WB0_OFF + tid * 16;
    const char* s = (const char*)wsrc + tid * 16;
#pragma unroll
    for (int i = 0; i < 4; i++) cp16(d + i * 4096, s + i * 4096);
    CP_COMMIT();
}

// ---- one fused 64x256x256 GEMM (single fp16 A & W); chunk0 already in flight ----
__device__ __forceinline__ void gemm256(const char* smem, uint32_t sb, const uint32_t* wsrc,
                                        float (&c)[2][8][4], int tid, int wn,
                                        const char* apr) {
#pragma unroll
    for (int mt = 0; mt < 2; mt++)
#pragma unroll
        for (int nt = 0; nt < 8; nt++)
#pragma unroll
            for (int q = 0; q < 4; q++) c[mt][nt][q] = 0.f;

    const uint32_t dst0 = sb + WB0_OFF + tid * 16;
    const uint32_t dst1 = sb + WB1_OFF + tid * 16;
    const char* src = (const char*)wsrc + tid * 16;
    const char* wb0 = smem + WB0_OFF + wn * 2048 + (tid & 31) * 16;
    const char* wb1 = smem + WB1_OFF + wn * 2048 + (tid & 31) * 16;

#pragma unroll
    for (int ch = 0; ch < 8; ch++) {
        CP_WAIT0();
        __syncthreads();
        if (ch + 1 < 8) {
            uint32_t d = ((ch + 1) & 1) ? dst1 : dst0;
            const char* s = src + (ch + 1) * 16384;
#pragma unroll
            for (int i = 0; i < 4; i++) cp16(d + i * 4096, s + i * 4096);
            CP_COMMIT();
        }
        const char* wb = (ch & 1) ? wb1 : wb0;
#pragma unroll
        for (int kl = 0; kl < 2; kl++) {
            const int kt = ch * 2 + kl;
            const char* ac = apr + kt * 2048;
            uint4 ah0 = *(const uint4*)(ac);
            uint4 ah1 = *(const uint4*)(ac + 512);
            uint32_t ahi[2][4] = {{ah0.x, ah0.y, ah0.z, ah0.w}, {ah1.x, ah1.y, ah1.z, ah1.w}};
            const char* wbk = wb + kl * 8192;
#pragma unroll
            for (int jj = 0; jj < 4; jj++) {
                uint4 b = *(const uint4*)(wbk + jj * 512);
#pragma unroll
                for (int mt = 0; mt < 2; mt++) {
                    hmma(c[mt][jj * 2],     ahi[mt], b.x, b.y);
                    hmma(c[mt][jj * 2 + 1], ahi[mt], b.z, b.w);
                }
            }
        }
    }
}

// rows per thread: idx(mt,h) = wm*32 + mt*16 + h*8 + g
__device__ __forceinline__ void ln_stats(float (&c)[2][8][4], float* psum, float* psq,
                                         int wn, int rowbase, int t,
                                         float (&mu)[2][2], float (&rs)[2][2]) {
    float s[2][2] = {{0, 0}, {0, 0}}, q[2][2] = {{0, 0}, {0, 0}};
#pragma unroll
    for (int mt = 0; mt < 2; mt++)
#pragma unroll
        for (int nt = 0; nt < 8; nt++) {
            s[mt][0] += c[mt][nt][0] + c[mt][nt][1];
            q[mt][0] += c[mt][nt][0] * c[mt][nt][0] + c[mt][nt][1] * c[mt][nt][1];
            s[mt][1] += c[mt][nt][2] + c[mt][nt][3];
            q[mt][1] += c[mt][nt][2] * c[mt][nt][2] + c[mt][nt][3] * c[mt][nt][3];
        }
#pragma unroll
    for (int mt = 0; mt < 2; mt++)
#pragma unroll
        for (int h = 0; h < 2; h++) {
            s[mt][h] += __shfl_xor_sync(~0u, s[mt][h], 1);
            s[mt][h] += __shfl_xor_sync(~0u, s[mt][h], 2);
            q[mt][h] += __shfl_xor_sync(~0u, q[mt][h], 1);
            q[mt][h] += __shfl_xor_sync(~0u, q[mt][h], 2);
        }
    if (t == 0) {
#pragma unroll
        for (int mt = 0; mt < 2; mt++)
#pragma unroll
            for (int h = 0; h < 2; h++) {
                int idx = rowbase + mt * 16 + h * 8;
                psum[wn * 64 + idx] = s[mt][h];
                psq[wn * 64 + idx]  = q[mt][h];
            }
    }
    __syncthreads();
#pragma unroll
    for (int mt = 0; mt < 2; mt++)
#pragma unroll
        for (int h = 0; h < 2; h++) {
            int idx = rowbase + mt * 16 + h * 8;
            float ts = psum[idx] + psum[64 + idx] + psum[128 + idx] + psum[192 + idx];
            float tq = psq[idx] + psq[64 + idx] + psq[128 + idx] + psq[192 + idx];
            float m = ts * (1.f / 256.f);
            mu[mt][h] = m;
            rs[mt][h] = rsqrtf(tq * (1.f / 256.f) - m * m + EPS);
        }
}

// writer: cell(kt=wn*4+p, tile=2wm+mt, lane) at apw + p*2048 + mt*512
__device__ __forceinline__ void norm_split(float (&c)[2][8][4], const float* gv, const float* bv,
                                           float (&mu)[2][2], float (&rs)[2][2],
                                           char* apw, int wn, int t) {
#pragma unroll
    for (int p = 0; p < 4; p++) {
#pragma unroll
        for (int mt = 0; mt < 2; mt++) {
            uint32_t hi[4];
#pragma unroll
            for (int e = 0; e < 2; e++) {
                int nt = 2 * p + e;
                int cg = wn * 64 + nt * 8 + t * 2;
                float2 gg = *(const float2*)(gv + cg);
                float2 bb = *(const float2*)(bv + cg);
                float v0 = (c[mt][nt][0] - mu[mt][0]) * rs[mt][0] * gg.x + bb.x;
                float v1 = (c[mt][nt][1] - mu[mt][0]) * rs[mt][0] * gg.y + bb.y;
                float v2 = (c[mt][nt][2] - mu[mt][1]) * rs[mt][1] * gg.x + bb.x;
                float v3 = (c[mt][nt][3] - mu[mt][1]) * rs[mt][1] * gg.y + bb.y;
                hi[e * 2]     = pack2(v0, v1);
                hi[e * 2 + 1] = pack2(v2, v3);
            }
            *(uint4*)(apw + p * 2048 + mt * 512) = make_uint4(hi[0], hi[1], hi[2], hi[3]);
        }
    }
}

__device__ __forceinline__ void gelu_split(float (&c)[2][8][4], const float* bv,
                                           char* apw, int wn, int t) {
    __syncthreads();   // all warps out of previous GEMM before Apack overwrite
#pragma unroll
    for (int p = 0; p < 4; p++) {
#pragma unroll
        for (int mt = 0; mt < 2; mt++) {
            uint32_t hi[4];
#pragma unroll
            for (int e = 0; e < 2; e++) {
                int nt = 2 * p + e;
                int cg = wn * 64 + nt * 8 + t * 2;
                float2 bb = *(const float2*)(bv + cg);
                float v0 = gelu(c[mt][nt][0] + bb.x);
                float v1 = gelu(c[mt][nt][1] + bb.y);
                float v2 = gelu(c[mt][nt][2] + bb.x);
                float v3 = gelu(c[mt][nt][3] + bb.y);
                hi[e * 2]     = pack2(v0, v1);
                hi[e * 2 + 1] = pack2(v2, v3);
            }
            *(uint4*)(apw + p * 2048 + mt * 512) = make_uint4(hi[0], hi[1], hi[2], hi[3]);
        }
    }
}

__global__ void __launch_bounds__(NTHR, 2)
stab_hmma(const float* __restrict__ meas, const float* __restrict__ event,
          const float* __restrict__ leak, const float* __restrict__ event_leak,
          const int* __restrict__ stab_ids, const int* __restrict__ cycle_ids,
          const float* __restrict__ w_meas, const float* __restrict__ b_meas,
          const float* __restrict__ w_event, const float* __restrict__ b_event,
          const float* __restrict__ w_leak, const float* __restrict__ b_leak,
          const float* __restrict__ w_el, const float* __restrict__ b_el,
          const float* __restrict__ stab_table, const float* __restrict__ cycle_table,
          const float* __restrict__ g1, const float* __restrict__ be1,
          const float* __restrict__ b11, const float* __restrict__ b12,
          const float* __restrict__ g2, const float* __restrict__ be2,
          const float* __restrict__ b21, const float* __restrict__ b22,
          float* __restrict__ out) {
    extern __shared__ char smem[];
    const uint32_t sb = s2u(smem);
    float*  prm  = (float*)(smem + PRM_OFF);
    float*  psum = (float*)(smem + PS_OFF);
    float*  psq  = (float*)(smem + PSQ_OFF);
    float*  apf  = (float*)(smem + AP_OFF);   // embed-param staging (before Apack is used)

    const int tid = threadIdx.x, w = tid >> 5, lane = tid & 31;
    const int wn = w & 3, wm = w >> 2;        // wn 0..3, wm 0..1
    const int t = lane & 3, g = lane >> 2;
    const int rowbase = wm * 32 + g;
    const int base = blockIdx.x * 64;

    // residual x in SMEM as half2 pairs: slot(mt,nt) = mt*8+nt, 8B per thread
    char* xsp = smem + XS_OFF + tid * 8;

    // A cell addresses (conflict-free: lane-linear within each tile block)
    const char* apr = smem + AP_OFF + wm * 1024 + lane * 16;               // + kt*2048 + mt*512
    char*       apw = smem + AP_OFF + wn * 8192 + wm * 1024 + lane * 16;   // + p*2048 + mt*512

    {   // permanent params (8KB) + embed staging in Apack region (5KB)
        const float* P[8] = {g1, be1, b11, b12, g2, be2, b21, b22};
        for (int i = tid; i < 8 * 256; i += NTHR) prm[i] = P[i >> 8][i & 255];
        const float* Q[4] = {w_meas, w_event, w_leak, w_el};
        for (int i = tid; i < 4 * 256; i += NTHR) apf[256 + i] = Q[i >> 8][i & 255];
        for (int i = tid; i < 256; i += NTHR)
            apf[i] = b_meas[i] + b_event[i] + b_leak[i] + b_el[i];
    }
    __syncthreads();

    float c[2][8][4];

    // ---- embed (values land directly in C/A-fragment layout); x -> SMEM fp16 ----
#pragma unroll
    for (int mt = 0; mt < 2; mt++) {
        int r0 = base + rowbase + mt * 16;
        int r1 = r0 + 8;
        float me0 = meas[r0], me1 = meas[r1];
        float ev0 = event[r0], ev1 = event[r1];
        float lk0 = leak[r0], lk1 = leak[r1];
        float el0 = event_leak[r0], el1 = event_leak[r1];
        const float* st0 = stab_table + (size_t)stab_ids[r0] * 256;
        const float* st1 = stab_table + (size_t)stab_ids[r1] * 256;
        const float* cy0 = cycle_table + (size_t)cycle_ids[r0] * 256;
        const float* cy1 = cycle_table + (size_t)cycle_ids[r1] * 256;
#pragma unroll
        for (int nt = 0; nt < 8; nt++) {
            int cg = wn * 64 + nt * 8 + t * 2;
            float2 bc  = *(const float2*)(apf + 0 * 256 + cg);
            float2 wmv = *(const float2*)(apf + 1 * 256 + cg);
            float2 wev = *(const float2*)(apf + 2 * 256 + cg);
            float2 wlv = *(const float2*)(apf + 3 * 256 + cg);
            float2 wzv = *(const float2*)(apf + 4 * 256 + cg);
            float2 s0 = *(const float2*)(st0 + cg), s1 = *(const float2*)(st1 + cg);
            float2 q0 = *(const float2*)(cy0 + cg), q1 = *(const float2*)(cy1 + cg);
            c[mt][nt][0] = bc.x + me0 * wmv.x + ev0 * wev.x + lk0 * wlv.x + el0 * wzv.x + s0.x + q0.x;
            c[mt][nt][1] = bc.y + me0 * wmv.y + ev0 * wev.y + lk0 * wlv.y + el0 * wzv.y + s0.y + q0.y;
            c[mt][nt][2] = bc.x + me1 * wmv.x + ev1 * wev.x + lk1 * wlv.x + el1 * wzv.x + s1.x + q1.x;
            c[mt][nt][3] = bc.y + me1 * wmv.y + ev1 * wev.y + lk1 * wlv.y + el1 * wzv.y + s1.y + q1.y;
        }
    }
    // NOTE: xs writes deferred until after Apack staging area is done being read
    __syncthreads();   // apf reads complete before any other use; also covers prm
#pragma unroll
    for (int mt = 0; mt < 2; mt++)
#pragma unroll
        for (int nt = 0; nt < 8; nt++)
            *(uint2*)(xsp + (mt * 8 + nt) * 2048) =
                make_uint2(pack2(c[mt][nt][0], c[mt][nt][1]),
                           pack2(c[mt][nt][2], c[mt][nt][3]));

    // prefetch GEMM1 chunk0 under the LN1 epilogue
    prefetch_c0(sb, &g_wpack[0][0][0], tid);

    float mu[2][2], rs[2][2];
    ln_stats(c, psum, psq, wn, rowbase, t, mu, rs);   // syncthreads inside
    norm_split(c, prm + 0 * 256, prm + 1 * 256, mu, rs, apw, wn, t);

    // GEMM1 ; GELU(+b11)
    gemm256(smem, sb, &g_wpack[0][0][0], c, tid, wn, apr);
    prefetch_c0(sb, &g_wpack[1][0][0], tid);
    gelu_split(c, prm + 2 * 256, apw, wn, t);

    // GEMM2 ; x += D + b12 ; LN2
    gemm256(smem, sb, &g_wpack[1][0][0], c, tid, wn, apr);
    prefetch_c0(sb, &g_wpack[2][0][0], tid);
#pragma unroll
    for (int mt = 0; mt < 2; mt++)
#pragma unroll
        for (int nt = 0; nt < 8; nt++) {
            int cg = wn * 64 + nt * 8 + t * 2;
            float2 bb = *(const float2*)(prm + 3 * 256 + cg);
            uint2 xv = *(const uint2*)(xsp + (mt * 8 + nt) * 2048);
            float2 x0 = unpack2h(xv.x), x1 = unpack2h(xv.y);
            c[mt][nt][0] = x0.x + c[mt][nt][0] + bb.x;
            c[mt][nt][1] = x0.y + c[mt][nt][1] + bb.y;
            c[mt][nt][2] = x1.x + c[mt][nt][2] + bb.x;
            c[mt][nt][3] = x1.y + c[mt][nt][3] + bb.y;
            *(uint2*)(xsp + (mt * 8 + nt) * 2048) =
                make_uint2(pack2(c[mt][nt][0], c[mt][nt][1]),
                           pack2(c[mt][nt][2], c[mt][nt][3]));
        }
    ln_stats(c, psum, psq, wn, rowbase, t, mu, rs);
    norm_split(c, prm + 4 * 256, prm + 5 * 256, mu, rs, apw, wn, t);

    // GEMM3 ; GELU(+b21)
    gemm256(smem, sb, &g_wpack[2][0][0], c, tid, wn, apr);
    prefetch_c0(sb, &g_wpack[3][0][0], tid);
    gelu_split(c, prm + 6 * 256, apw, wn, t);

    // GEMM4 ; out = x + D + b22
    gemm256(smem, sb, &g_wpack[3][0][0], c, tid, wn, apr);
#pragma unroll
    for (int mt = 0; mt < 2; mt++) {
        float* orow0 = out + (size_t)(base + rowbase + mt * 16) * 256;
        float* orow1 = orow0 + 8 * 256;
#pragma unroll
        for (int nt = 0; nt < 8; nt++) {
            int cg = wn * 64 + nt * 8 + t * 2;
            float2 bb = *(const float2*)(prm + 7 * 256 + cg);
            uint2 xv = *(const uint2*)(xsp + (mt * 8 + nt) * 2048);
            float2 x0 = unpack2h(xv.x), x1 = unpack2h(xv.y);
            *(float2*)(orow0 + cg) =
                make_float2(x0.x + c[mt][nt][0] + bb.x, x0.y + c[mt][nt][1] + bb.y);
            *(float2*)(orow1 + cg) =
                make_float2(x1.x + c[mt][nt][2] + bb.x, x1.y + c[mt][nt][3] + bb.y);
        }
    }
}

extern "C" void kernel_launch(void* const* d_in, const int* in_sizes, int n_in,
                              void* d_out, int out_size) {
    const float* meas       = (const float*)d_in[0];
    const float* event      = (const float*)d_in[1];
    const float* leak       = (const float*)d_in[2];
    const float* event_leak = (const float*)d_in[3];
    const int*   stab_ids   = (const int*)d_in[4];
    const int*   cycle_ids  = (const int*)d_in[5];
    const float* w_meas  = (const float*)d_in[6];
    const float* b_meas  = (const float*)d_in[7];
    const float* w_event = (const float*)d_in[8];
    const float* b_event = (const float*)d_in[9];
    const float* w_leak  = (const float*)d_in[10];
    const float* b_leak  = (const float*)d_in[11];
    const float* w_el    = (const float*)d_in[12];
    const float* b_el    = (const float*)d_in[13];
    const float* stab_table  = (const float*)d_in[14];
    const float* cycle_table = (const float*)d_in[15];
    const float* g1  = (const float*)d_in[16];
    const float* be1 = (const float*)d_in[17];
    const float* W11 = (const float*)d_in[18];
    const float* b11 = (const float*)d_in[19];
    const float* W12 = (const float*)d_in[20];
    const float* b12 = (const float*)d_in[21];
    const float* g2  = (const float*)d_in[22];
    const float* be2 = (const float*)d_in[23];
    const float* W21 = (const float*)d_in[24];
    const float* b21 = (const float*)d_in[25];
    const float* W22 = (const float*)d_in[26];
    const float* b22 = (const float*)d_in[27];

    const int n_tokens = in_sizes[0];
    const int nblocks  = n_tokens / 64;    // 4096

    prep_w<<<32, 256>>>(W11, W12, W21, W22);

    cudaFuncSetAttribute(stab_hmma,
                         cudaFuncAttributeMaxDynamicSharedMemorySize, SMEM_TOTAL);
    stab_hmma<<<nblocks, NTHR, SMEM_TOTAL>>>(
        meas, event, leak, event_leak, stab_ids, cycle_ids,
        w_meas, b_meas, w_event, b_event, w_leak, b_leak, w_el, b_el,
        stab_table, cycle_table,
        g1, be1, b11, b12, g2, be2, b21, b22,
        (float*)d_out);
}